// round 3
// baseline (speedup 1.0000x reference)
#include <cuda_runtime.h>
#include <cstdint>

#define NXQ 41
#define NXY 1681
#define GQ 68921
#define KPICK 4
#define NEGV (-1.0e9f)
#define VTH  (-1.0e8f)
#define NT 256
#define NC 2154              /* per-row chunks of 32 voxels (shifted grid) */
#define MW 2156              /* padded 32-bit mask words (>= ceil(GQ/32)+1) */

__device__ unsigned int g_maskw[MW];

// Sphere mask bitfield, bit-exact vs np.linalg.norm(grid_xyz) <= 6.0 in f32
// (monotone sqrt => equivalent to ss <= 36.0f with numpy's accumulation order).
__global__ void build_mask_kernel(const float* __restrict__ grid_xyz) {
    int g = blockIdx.x * blockDim.x + threadIdx.x;
    bool inside = false;
    if (g < GQ) {
        float x = grid_xyz[3 * g + 0];
        float y = grid_xyz[3 * g + 1];
        float z = grid_xyz[3 * g + 2];
        float ss = __fadd_rn(__fadd_rn(__fmul_rn(x, x), __fmul_rn(y, y)), __fmul_rn(z, z));
        inside = (ss <= 36.0f);
    }
    unsigned int b = __ballot_sync(0xffffffffu, inside);
    if ((threadIdx.x & 31) == 0) {
        int w = g >> 5;
        if (w < MW) g_maskw[w] = b;
    }
}

__global__ __launch_bounds__(NT, 4) void peaks_kernel(
    const float* __restrict__ density,
    const float* __restrict__ grid_xyz,
    const float* __restrict__ Rmats,
    const float* __restrict__ tpos,
    const float* __restrict__ node_mask,
    float* __restrict__ out,
    int rows, int C)
{
    __shared__ float s_cmax[NC];
    __shared__ int   s_carg[NC];
    __shared__ unsigned int s_mw[MW];
    __shared__ unsigned char s_flag[NC];
    __shared__ float s_ax[NXQ];
    __shared__ float s_wv[8];
    __shared__ int   s_wi[8];
    __shared__ int   s_pi[KPICK], s_pj[KPICK], s_pk[KPICK], s_pv[KPICK];
    __shared__ float s_ps[KPICK];

    const int tid  = threadIdx.x;
    const int lane = tid & 31;
    const int warp = tid >> 5;
    const int row  = blockIdx.x;
    const int s    = (4 - (row & 3)) & 3;        // per-row alignment shift (elements)
    const float* __restrict__ d = density + (long long)row * GQ;

    for (int i = tid; i < MW; i += NT) s_mw[i] = g_maskw[i];
    for (int i = tid; i < NC; i += NT) s_flag[i] = 0;
    if (tid < NXQ) s_ax[tid] = grid_xyz[(long long)tid * NXY * 3];
    __syncthreads();

    // ---- streaming pass: per-thread 32-voxel chunk (max, first-argmax) ----
    for (int m = tid; m < NC; m += NT) {
        int base = s + 32 * m;
        float bv = NEGV;
        int   bi;
        if (m == 0 || base + 32 > GQ) {
            // scalar path: chunk 0 head [0,s) + aligned body, or partial tail chunk
            int lo = (m == 0) ? 0 : base;
            int hi = base + 32; if (hi > GQ) hi = GQ;
            bi = lo;
            for (int g = lo; g < hi; g++) {
                if ((s_mw[g >> 5] >> (g & 31)) & 1u) {
                    float v = __ldg(d + g);
                    if (v > bv) { bv = v; bi = g; }
                }
            }
        } else {
            unsigned bits = __funnelshift_r(s_mw[m], s_mw[m + 1], s);
            bi = base;
            if (bits != 0u) {
                const float4* p4 = reinterpret_cast<const float4*>(d + base);
                int be = 0;
#define PROC1(VV, EE) { if (((int)(bits << (31 - (EE)))) < 0) { float v_ = (VV); if (v_ > bv) { bv = v_; be = (EE); } } }
#pragma unroll
                for (int q = 0; q < 8; q++) {
                    float4 a = __ldg(p4 + q);
                    int e0 = 4 * q;
                    PROC1(a.x, e0)
                    PROC1(a.y, e0 + 1)
                    PROC1(a.z, e0 + 2)
                    PROC1(a.w, e0 + 3)
                }
#undef PROC1
                bi = base + be;
            }
        }
        s_cmax[m] = bv;
        s_carg[m] = bi;
    }
    __syncthreads();

#define CHUNK_OF(G) (((G) < s) ? 0 : (((G) - s) >> 5))

    // ---- K sequential picks with NMS ----
    for (int p = 0; p < KPICK; p++) {
        float bv = -3.0e38f; int bi = 0x7FFFFFFF;
        for (int c = tid; c < NC; c += NT) {
            float v = s_cmax[c]; int g = s_carg[c];
            if (v > bv || (v == bv && g < bi)) { bv = v; bi = g; }
        }
#pragma unroll
        for (int o = 16; o > 0; o >>= 1) {
            float ov = __shfl_down_sync(0xffffffffu, bv, o);
            int   oi = __shfl_down_sync(0xffffffffu, bi, o);
            if (ov > bv || (ov == bv && oi < bi)) { bv = ov; bi = oi; }
        }
        if (lane == 0) { s_wv[warp] = bv; s_wi[warp] = bi; }
        __syncthreads();
        if (warp == 0) {
            bv = (lane < 8) ? s_wv[lane] : -3.0e38f;
            bi = (lane < 8) ? s_wi[lane] : 0x7FFFFFFF;
#pragma unroll
            for (int o = 4; o > 0; o >>= 1) {
                float ov = __shfl_down_sync(0xffffffffu, bv, o);
                int   oi = __shfl_down_sync(0xffffffffu, bi, o);
                if (ov > bv || (ov == bv && oi < bi)) { bv = ov; bi = oi; }
            }
            if (lane == 0) {
                int pidx = bi;
                int valid = (bv > VTH) ? 1 : 0;
                int pi = pidx / NXY; int rr = pidx - pi * NXY;
                int pj = rr / NXQ;   int pk = rr - pj * NXQ;
                s_pi[p] = pi; s_pj[p] = pj; s_pk[p] = pk;
                s_ps[p] = bv; s_pv[p] = valid;
            }
        }
        __syncthreads();

        if (s_pv[p] && p < KPICK - 1) {
            const int pi = s_pi[p], pj = s_pj[p], pk = s_pk[p];
            if (tid < 49) {
                int di = tid / 7 - 3, dj = tid % 7 - 3;
                int i = pi + di, j = pj + dj;
                if (i >= 0 && i < NXQ && j >= 0 && j < NXQ) {
                    int kmin = pk - 3 < 0 ? 0 : pk - 3;
                    int kmax = pk + 3 > NXQ - 1 ? NXQ - 1 : pk + 3;
                    int ls = i * NXY + j * NXQ + kmin;
                    int le = ls + (kmax - kmin);
                    s_flag[CHUNK_OF(ls)] = 1;
                    s_flag[CHUNK_OF(le)] = 1;
                }
            }
            __syncthreads();
            int ilo = pi - 3 < 0 ? 0 : pi - 3, ihi = pi + 3 > NXQ - 1 ? NXQ - 1 : pi + 3;
            int jlo = pj - 3 < 0 ? 0 : pj - 3, jhi = pj + 3 > NXQ - 1 ? NXQ - 1 : pj + 3;
            int klo = pk - 3 < 0 ? 0 : pk - 3, khi = pk + 3 > NXQ - 1 ? NXQ - 1 : pk + 3;
            int cmin = CHUNK_OF(ilo * NXY + jlo * NXQ + klo);
            int cmax = CHUNK_OF(ihi * NXY + jhi * NXQ + khi);
            for (int c = cmin + tid; c <= cmax; c += NT) {
                if (!s_flag[c]) continue;
                int lo = (c == 0) ? 0 : (s + 32 * c);
                int hi = s + 32 * c + 32; if (hi > GQ) hi = GQ;
                float bv2 = NEGV; int bi2 = lo;
                for (int g = lo; g < hi; g++) {
                    if (!((s_mw[g >> 5] >> (g & 31)) & 1u)) continue;
                    int gi = g / NXY; int grr = g - gi * NXY;
                    int gj = grr / NXQ; int gk = grr - gj * NXQ;
                    bool sup = false;
                    for (int q = 0; q <= p; q++) {
                        if (s_pv[q] &&
                            abs(gi - s_pi[q]) <= 3 &&
                            abs(gj - s_pj[q]) <= 3 &&
                            abs(gk - s_pk[q]) <= 3) sup = true;
                    }
                    if (sup) continue;
                    float v = __ldg(d + g);
                    if (v > bv2) { bv2 = v; bi2 = g; }
                }
                s_cmax[c] = bv2; s_carg[c] = bi2; s_flag[c] = 0;
            }
        }
        __syncthreads();
    }

    // ---- epilogue ----
    if (tid < KPICK) {
        int k = tid;
        int n = row / C;
        float m = node_mask[n];
        int v = s_pv[k];
        float x = 0.f, y = 0.f, z = 0.f;
        if (v) { x = s_ax[s_pi[k]]; y = s_ax[s_pj[k]]; z = s_ax[s_pk[k]]; }
        float score = v ? s_ps[k] : NEGV;
        const float* R = Rmats + (long long)n * 9;
        const float* t = tpos + (long long)n * 3;
        float gx = R[0] * x + R[1] * y + R[2] * z + t[0];
        float gy = R[3] * x + R[4] * y + R[5] * z + t[1];
        float gz = R[6] * x + R[7] * y + R[8] * z + t[2];
        long long P  = (long long)rows * KPICK;
        long long rk = (long long)row * KPICK + k;
        out[rk * 3 + 0] = x * m;
        out[rk * 3 + 1] = y * m;
        out[rk * 3 + 2] = z * m;
        out[3 * P + rk * 3 + 0] = gx * m;
        out[3 * P + rk * 3 + 1] = gy * m;
        out[3 * P + rk * 3 + 2] = gz * m;
        out[6 * P + rk] = score * m;
        out[7 * P + rk] = (v && m != 0.0f) ? 1.0f : 0.0f;
    }
}

extern "C" void kernel_launch(void* const* d_in, const int* in_sizes, int n_in,
                              void* d_out, int out_size) {
    // metadata order: density, grid_xyz, sphere_mask, coords_int, Rmats, tpos, node_mask
    const float* density   = (const float*)d_in[0];
    const float* grid_xyz  = (const float*)d_in[1];
    const float* Rmats     = (const float*)d_in[4];
    const float* tpos      = (const float*)d_in[5];
    const float* node_mask = (const float*)d_in[6];
    int rows = in_sizes[0] / GQ;   // B*N*C
    int BN   = in_sizes[6];        // B*N
    int C    = rows / BN;

    build_mask_kernel<<<(MW * 32 + NT - 1) / NT, NT>>>(grid_xyz);
    peaks_kernel<<<rows, NT>>>(density, grid_xyz, Rmats, tpos, node_mask,
                               (float*)d_out, rows, C);
}

// round 4
// speedup vs baseline: 1.8850x; 1.8850x over previous
#include <cuda_runtime.h>
#include <cstdint>

#define NXQ 41
#define NXY 1681
#define GQ 68921
#define KPICK 4
#define NEGV (-1.0e9f)
#define VTH  (-1.0e8f)
#define NT 512
#define NWARP (NT/32)
#define NC128 539            /* ceil(GQ/128) per-row 128-voxel chunks (shifted) */
#define MW 2160              /* padded 32-bit mask words */

__device__ unsigned int g_maskw[MW];

// Sphere mask bitfield, bit-exact vs np.linalg.norm(grid_xyz) <= 6.0 in f32
// (monotone correctly-rounded sqrt => equivalent to ss <= 36.0f).
__global__ void build_mask_kernel(const float* __restrict__ grid_xyz) {
    int g = blockIdx.x * blockDim.x + threadIdx.x;
    bool inside = false;
    if (g < GQ) {
        float x = grid_xyz[3 * g + 0];
        float y = grid_xyz[3 * g + 1];
        float z = grid_xyz[3 * g + 2];
        float ss = __fadd_rn(__fadd_rn(__fmul_rn(x, x), __fmul_rn(y, y)), __fmul_rn(z, z));
        inside = (ss <= 36.0f);
    }
    unsigned int b = __ballot_sync(0xffffffffu, inside);
    if ((threadIdx.x & 31) == 0) {
        int w = g >> 5;
        if (w < MW) g_maskw[w] = b;
    }
}

// Warp-wide (max, first-argmax) combine + store; lane order == index order,
// so lowest winning lane == lowest index (first occurrence).
__device__ __forceinline__ void warp_store(int c, float bv, int bi, int lane,
                                           float* s_cmax, int* s_carg) {
    unsigned u = __float_as_uint(bv);
    unsigned ord = u ^ ((unsigned)((int)u >> 31) | 0x80000000u);
    unsigned mx = __reduce_max_sync(0xffffffffu, ord);
    unsigned win = __ballot_sync(0xffffffffu, ord == mx);
    int src = __ffs((int)win) - 1;
    float wv = __shfl_sync(0xffffffffu, bv, src);
    int   wi = __shfl_sync(0xffffffffu, bi, src);
    if (lane == 0) { s_cmax[c] = wv; s_carg[c] = wi; }
}

__global__ __launch_bounds__(NT) void peaks_kernel(
    const float* __restrict__ density,
    const float* __restrict__ grid_xyz,
    const float* __restrict__ Rmats,
    const float* __restrict__ tpos,
    const float* __restrict__ node_mask,
    float* __restrict__ out,
    int rows, int C)
{
    __shared__ unsigned int s_mw[MW];
    __shared__ float s_cmax[NC128];
    __shared__ int   s_carg[NC128];
    __shared__ unsigned char s_flag[NC128];
    __shared__ float s_ax[NXQ];
    __shared__ float s_wv[NWARP];
    __shared__ int   s_wi[NWARP];
    __shared__ int   s_pi[KPICK], s_pj[KPICK], s_pk[KPICK], s_pv[KPICK];
    __shared__ float s_ps[KPICK];

    const int tid  = threadIdx.x;
    const int lane = tid & 31;
    const int warp = tid >> 5;
    const int row  = blockIdx.x;
    const int s    = (4 - (row & 3)) & 3;          // alignment shift: (row*GQ+s)%4==0
    const float* __restrict__ d = density + (long long)row * GQ;

    for (int i = tid; i < MW; i += NT) s_mw[i] = g_maskw[i];
    for (int i = tid; i < NC128; i += NT) s_flag[i] = 0;
    if (tid < NXQ) s_ax[tid] = grid_xyz[(long long)tid * NXY * 3];
    __syncthreads();

    // ---- streaming pass: warp-coalesced 128-voxel chunks, 2-way unrolled ----
    for (int cA = warp; cA < NC128; cA += 2 * NWARP) {
        const int cB = cA + NWARP;
        const bool hasB = (cB < NC128);

        int gA = s + (cA << 7) + (lane << 2);
        unsigned nibA = __funnelshift_r(s_mw[gA >> 5], s_mw[(gA >> 5) + 1], gA) & 0xFu;
        bool tailA = (s + (cA << 7) + 128 > GQ);
        unsigned anyA = __ballot_sync(0xffffffffu, nibA != 0u);
        float4 aA;
        if (anyA && !tailA) aA = __ldg(reinterpret_cast<const float4*>(d + gA));

        int gB = 0; unsigned nibB = 0, anyB = 0; bool tailB = false; float4 aB;
        if (hasB) {
            gB = s + (cB << 7) + (lane << 2);
            nibB = __funnelshift_r(s_mw[gB >> 5], s_mw[(gB >> 5) + 1], gB) & 0xFu;
            tailB = (s + (cB << 7) + 128 > GQ);
            anyB = __ballot_sync(0xffffffffu, nibB != 0u);
            if (anyB && !tailB) aB = __ldg(reinterpret_cast<const float4*>(d + gB));
        }

        {
            float bv = NEGV; int bi = (cA == 0 && lane == 0) ? 0 : gA;
            if (anyA) {
                if (tailA) {
#pragma unroll
                    for (int e = 0; e < 4; e++) {
                        int g = gA + e;
                        if (g < GQ && ((nibA >> e) & 1u)) {
                            float v = __ldg(d + g);
                            if (v > bv) { bv = v; bi = g; }
                        }
                    }
                } else {
                    if ((nibA & 1u) && aA.x > bv) { bv = aA.x; bi = gA; }
                    if ((nibA & 2u) && aA.y > bv) { bv = aA.y; bi = gA + 1; }
                    if ((nibA & 4u) && aA.z > bv) { bv = aA.z; bi = gA + 2; }
                    if ((nibA & 8u) && aA.w > bv) { bv = aA.w; bi = gA + 3; }
                }
            }
            warp_store(cA, bv, bi, lane, s_cmax, s_carg);
        }
        if (hasB) {
            float bv = NEGV; int bi = gB;
            if (anyB) {
                if (tailB) {
#pragma unroll
                    for (int e = 0; e < 4; e++) {
                        int g = gB + e;
                        if (g < GQ && ((nibB >> e) & 1u)) {
                            float v = __ldg(d + g);
                            if (v > bv) { bv = v; bi = g; }
                        }
                    }
                } else {
                    if ((nibB & 1u) && aB.x > bv) { bv = aB.x; bi = gB; }
                    if ((nibB & 2u) && aB.y > bv) { bv = aB.y; bi = gB + 1; }
                    if ((nibB & 4u) && aB.z > bv) { bv = aB.z; bi = gB + 2; }
                    if ((nibB & 8u) && aB.w > bv) { bv = aB.w; bi = gB + 3; }
                }
            }
            warp_store(cB, bv, bi, lane, s_cmax, s_carg);
        }
    }
    __syncthreads();

#define CHUNK_OF(G) (((G) < s) ? 0 : (((G) - s) >> 7))

    // ---- K sequential picks with NMS ----
    for (int p = 0; p < KPICK; p++) {
        float bv = -3.0e38f; int bi = 0x7FFFFFFF;
        for (int c = tid; c < NC128; c += NT) {
            float v = s_cmax[c]; int g = s_carg[c];
            if (v > bv || (v == bv && g < bi)) { bv = v; bi = g; }
        }
#pragma unroll
        for (int o = 16; o > 0; o >>= 1) {
            float ov = __shfl_down_sync(0xffffffffu, bv, o);
            int   oi = __shfl_down_sync(0xffffffffu, bi, o);
            if (ov > bv || (ov == bv && oi < bi)) { bv = ov; bi = oi; }
        }
        if (lane == 0) { s_wv[warp] = bv; s_wi[warp] = bi; }
        __syncthreads();
        if (warp == 0) {
            bv = (lane < NWARP) ? s_wv[lane] : -3.0e38f;
            bi = (lane < NWARP) ? s_wi[lane] : 0x7FFFFFFF;
#pragma unroll
            for (int o = 8; o > 0; o >>= 1) {
                float ov = __shfl_down_sync(0xffffffffu, bv, o);
                int   oi = __shfl_down_sync(0xffffffffu, bi, o);
                if (ov > bv || (ov == bv && oi < bi)) { bv = ov; bi = oi; }
            }
            if (lane == 0) {
                int pidx = bi;
                int valid = (bv > VTH) ? 1 : 0;
                int pi = pidx / NXY; int rr = pidx - pi * NXY;
                int pj = rr / NXQ;   int pk = rr - pj * NXQ;
                s_pi[p] = pi; s_pj[p] = pj; s_pk[p] = pk;
                s_ps[p] = bv; s_pv[p] = valid;
            }
        }
        __syncthreads();

        if (s_pv[p] && p < KPICK - 1) {
            const int pi = s_pi[p], pj = s_pj[p], pk = s_pk[p];
            if (tid < 49) {
                int di = tid / 7 - 3, dj = tid % 7 - 3;
                int i = pi + di, j = pj + dj;
                if (i >= 0 && i < NXQ && j >= 0 && j < NXQ) {
                    int kmin = pk - 3 < 0 ? 0 : pk - 3;
                    int kmax = pk + 3 > NXQ - 1 ? NXQ - 1 : pk + 3;
                    int ls = i * NXY + j * NXQ + kmin;
                    int le = ls + (kmax - kmin);
                    s_flag[CHUNK_OF(ls)] = 1;
                    s_flag[CHUNK_OF(le)] = 1;
                }
            }
            __syncthreads();
            int ilo = pi - 3 < 0 ? 0 : pi - 3, ihi = pi + 3 > NXQ - 1 ? NXQ - 1 : pi + 3;
            int jlo = pj - 3 < 0 ? 0 : pj - 3, jhi = pj + 3 > NXQ - 1 ? NXQ - 1 : pj + 3;
            int klo = pk - 3 < 0 ? 0 : pk - 3, khi = pk + 3 > NXQ - 1 ? NXQ - 1 : pk + 3;
            int cmin = CHUNK_OF(ilo * NXY + jlo * NXQ + klo);
            int cmax = CHUNK_OF(ihi * NXY + jhi * NXQ + khi);
            for (int c = cmin + warp; c <= cmax; c += NWARP) {
                if (!s_flag[c]) continue;                 // warp-uniform
                int g0 = s + (c << 7) + (lane << 2);
                unsigned nib = __funnelshift_r(s_mw[g0 >> 5], s_mw[(g0 >> 5) + 1], g0) & 0xFu;
                float bv2 = NEGV; int bi2 = (c == 0 && lane == 0) ? 0 : g0;
#pragma unroll
                for (int e = 0; e < 4; e++) {
                    int g = g0 + e;
                    if (g < GQ && ((nib >> e) & 1u)) {
                        int gi = g / NXY; int rr2 = g - gi * NXY;
                        int gj = rr2 / NXQ; int gk = rr2 - gj * NXQ;
                        bool sup = false;
                        for (int q = 0; q <= p; q++) {
                            if (s_pv[q] &&
                                abs(gi - s_pi[q]) <= 3 &&
                                abs(gj - s_pj[q]) <= 3 &&
                                abs(gk - s_pk[q]) <= 3) sup = true;
                        }
                        if (!sup) {
                            float v = __ldg(d + g);
                            if (v > bv2) { bv2 = v; bi2 = g; }
                        }
                    }
                }
                warp_store(c, bv2, bi2, lane, s_cmax, s_carg);
                if (lane == 0) s_flag[c] = 0;
            }
        }
        __syncthreads();
    }

    // ---- epilogue ----
    if (tid < KPICK) {
        int k = tid;
        int n = row / C;
        float m = node_mask[n];
        int v = s_pv[k];
        float x = 0.f, y = 0.f, z = 0.f;
        if (v) { x = s_ax[s_pi[k]]; y = s_ax[s_pj[k]]; z = s_ax[s_pk[k]]; }
        float score = v ? s_ps[k] : NEGV;
        const float* R = Rmats + (long long)n * 9;
        const float* t = tpos + (long long)n * 3;
        float gx = R[0] * x + R[1] * y + R[2] * z + t[0];
        float gy = R[3] * x + R[4] * y + R[5] * z + t[1];
        float gz = R[6] * x + R[7] * y + R[8] * z + t[2];
        long long P  = (long long)rows * KPICK;
        long long rk = (long long)row * KPICK + k;
        out[rk * 3 + 0] = x * m;
        out[rk * 3 + 1] = y * m;
        out[rk * 3 + 2] = z * m;
        out[3 * P + rk * 3 + 0] = gx * m;
        out[3 * P + rk * 3 + 1] = gy * m;
        out[3 * P + rk * 3 + 2] = gz * m;
        out[6 * P + rk] = score * m;
        out[7 * P + rk] = (v && m != 0.0f) ? 1.0f : 0.0f;
    }
}

extern "C" void kernel_launch(void* const* d_in, const int* in_sizes, int n_in,
                              void* d_out, int out_size) {
    // metadata order: density, grid_xyz, sphere_mask, coords_int, Rmats, tpos, node_mask
    const float* density   = (const float*)d_in[0];
    const float* grid_xyz  = (const float*)d_in[1];
    const float* Rmats     = (const float*)d_in[4];
    const float* tpos      = (const float*)d_in[5];
    const float* node_mask = (const float*)d_in[6];
    int rows = in_sizes[0] / GQ;   // B*N*C
    int BN   = in_sizes[6];        // B*N
    int C    = rows / BN;

    build_mask_kernel<<<(MW * 32 + 255) / 256, 256>>>(grid_xyz);
    peaks_kernel<<<rows, NT>>>(density, grid_xyz, Rmats, tpos, node_mask,
                               (float*)d_out, rows, C);
}

// round 5
// speedup vs baseline: 2.2030x; 1.1687x over previous
#include <cuda_runtime.h>
#include <cstdint>

#define NXQ 41
#define NXY 1681
#define GQ 68921
#define KPICK 4
#define NEGV (-1.0e9f)
#define VTH  (-1.0e8f)
#define NT 512
#define NWARP (NT/32)
#define NC 539               /* per-row 128-voxel chunks (shifted grid) */
#define MW 2160              /* padded 32-bit mask words */

__device__ unsigned int g_maskw[MW];

// Sphere mask bitfield, bit-exact vs np.linalg.norm(grid_xyz) <= 6.0 in f32
// (monotone correctly-rounded sqrt => equivalent to ss <= 36.0f).
__global__ void build_mask_kernel(const float* __restrict__ grid_xyz) {
    int g = blockIdx.x * blockDim.x + threadIdx.x;
    bool inside = false;
    if (g < GQ) {
        float x = grid_xyz[3 * g + 0];
        float y = grid_xyz[3 * g + 1];
        float z = grid_xyz[3 * g + 2];
        float ss = __fadd_rn(__fadd_rn(__fmul_rn(x, x), __fmul_rn(y, y)), __fmul_rn(z, z));
        inside = (ss <= 36.0f);
    }
    unsigned int b = __ballot_sync(0xffffffffu, inside);
    if ((threadIdx.x & 31) == 0) {
        int w = g >> 5;
        if (w < MW) g_maskw[w] = b;
    }
}

// Order-preserving float<->uint maps (x<y  <=>  f2ord(x)<f2ord(y))
__device__ __forceinline__ unsigned f2ord(float f) {
    int u = __float_as_int(f);
    return (unsigned)(u ^ ((u >> 31) | 0x80000000));
}
__device__ __forceinline__ float ord2f(unsigned o) {
    int m = (~(int)o) >> 31;
    return __int_as_float((int)(o ^ (unsigned)(m | 0x80000000)));
}

__global__ __launch_bounds__(NT) void peaks_kernel(
    const float* __restrict__ density,
    const float* __restrict__ grid_xyz,
    const float* __restrict__ Rmats,
    const float* __restrict__ tpos,
    const float* __restrict__ node_mask,
    float* __restrict__ out,
    int rows, int C)
{
    __shared__ unsigned int s_mw[MW];
    __shared__ unsigned int s_cord[NC];
    __shared__ unsigned char s_any[NC];
    __shared__ unsigned char s_flag[NC];
    __shared__ float s_ax[NXQ];
    __shared__ unsigned s_wv[NWARP];
    __shared__ int      s_wi[NWARP];
    __shared__ int s_pi[KPICK], s_pj[KPICK], s_pk[KPICK], s_pv[KPICK];
    __shared__ float s_ps[KPICK];

    const int tid  = threadIdx.x;
    const int lane = tid & 31;
    const int warp = tid >> 5;
    const int row  = blockIdx.x;
    const int s    = (4 - (row & 3)) & 3;          // (row*GQ + s) % 4 == 0
    const float* __restrict__ d = density + (long long)row * GQ;
    const unsigned ORD_NEG = f2ord(NEGV);
    const unsigned ORD_VTH = f2ord(VTH);

    // init: masks to smem; per-chunk any-flags from global mask (indep of s_mw)
    for (int i = tid; i < MW; i += NT) s_mw[i] = g_maskw[i];
    for (int c = tid; c < NC; c += NT) {
        int lo = (c == 0) ? 0 : (s + (c << 7));
        int hi = s + (c << 7) + 128; if (hi > GQ) hi = GQ;
        unsigned any = 0;
        int w0 = lo >> 5, w1 = (hi - 1) >> 5;
        for (int w = w0; w <= w1; w++) {
            unsigned m = g_maskw[w];
            if (w == w0) m &= (0xFFFFFFFFu << (lo & 31));
            if (w == w1) m &= (0xFFFFFFFFu >> (31 - ((hi - 1) & 31)));
            any |= m;
        }
        s_any[c] = any ? 1 : 0;
        s_cord[c] = ORD_NEG;
        s_flag[c] = 0;
    }
    if (tid < NXQ) s_ax[tid] = grid_xyz[(long long)tid * NXY * 3];
    __syncthreads();

    // ---- streaming pass: warp per chunk, value-only max ----
    for (int c = warp; c < NC; c += NWARP) {
        if (!s_any[c]) continue;                      // warp-uniform
        int base = s + (c << 7);
        float bv = NEGV;
        bool edge = (c == 0 && s != 0) || (base + 128 > GQ);
        if (!edge) {
            int g0 = base + (lane << 2);
            int w = g0 >> 5;
            unsigned nib = __funnelshift_r(s_mw[w], s_mw[w + 1], g0) & 0xFu;
            if (nib) {
                float4 a = __ldg(reinterpret_cast<const float4*>(d + g0));
                if (nib & 1u) bv = fmaxf(bv, a.x);
                if (nib & 2u) bv = fmaxf(bv, a.y);
                if (nib & 4u) bv = fmaxf(bv, a.z);
                if (nib & 8u) bv = fmaxf(bv, a.w);
            }
        } else {
            int lo = (c == 0) ? 0 : base;
            int hi = base + 128; if (hi > GQ) hi = GQ;
            for (int g = lo + lane; g < hi; g += 32)
                if ((s_mw[g >> 5] >> (g & 31)) & 1u)
                    bv = fmaxf(bv, __ldg(d + g));
        }
        unsigned r = __reduce_max_sync(0xffffffffu, f2ord(bv));
        if (lane == 0) s_cord[c] = r;
    }
    __syncthreads();

#define CHUNK_OF(G) (((G) < s) ? 0 : (((G) - s) >> 7))
#define SUPPRESSED(GI, GJ, GK, P) ({ bool _s = false;                        \
        for (int _q = 0; _q <= (P); _q++)                                    \
            if (s_pv[_q] && abs((GI) - s_pi[_q]) <= 3 &&                     \
                abs((GJ) - s_pj[_q]) <= 3 && abs((GK) - s_pk[_q]) <= 3)      \
                _s = true;                                                   \
        _s; })

    // ---- K sequential picks ----
    for (int p = 0; p < KPICK; p++) {
        // block argmax over chunk ords (tie -> lowest chunk)
        unsigned bv = 0; int bc = 0x7FFFFFFF;
        for (int c = tid; c < NC; c += NT) {
            unsigned v = s_cord[c];
            if (v > bv || (v == bv && c < bc)) { bv = v; bc = c; }
        }
#pragma unroll
        for (int o = 16; o > 0; o >>= 1) {
            unsigned ov = __shfl_down_sync(0xffffffffu, bv, o);
            int      oc = __shfl_down_sync(0xffffffffu, bc, o);
            if (ov > bv || (ov == bv && oc < bc)) { bv = ov; bc = oc; }
        }
        if (lane == 0) { s_wv[warp] = bv; s_wi[warp] = bc; }
        __syncthreads();
        if (warp == 0) {
            bv = (lane < NWARP) ? s_wv[lane] : 0;
            bc = (lane < NWARP) ? s_wi[lane] : 0x7FFFFFFF;
#pragma unroll
            for (int o = 8; o > 0; o >>= 1) {
                unsigned ov = __shfl_down_sync(0xffffffffu, bv, o);
                int      oc = __shfl_down_sync(0xffffffffu, bc, o);
                if (ov > bv || (ov == bv && oc < bc)) { bv = ov; bc = oc; }
            }
            // broadcast winner, then resolve first index within winning chunk
            bv = __shfl_sync(0xffffffffu, bv, 0);
            bc = __shfl_sync(0xffffffffu, bc, 0);
            int base = s + (bc << 7);
            int cand = 0x7FFFFFFF;
            bool edge = (bc == 0 && s != 0) || (base + 128 > GQ);
            if (!edge) {
                int g0 = base + (lane << 2);
                int w = g0 >> 5;
                unsigned nib = __funnelshift_r(s_mw[w], s_mw[w + 1], g0) & 0xFu;
                if (nib) {
                    float4 a = __ldg(reinterpret_cast<const float4*>(d + g0));
#pragma unroll
                    for (int e = 3; e >= 0; e--) {
                        float v = (e == 0) ? a.x : (e == 1) ? a.y : (e == 2) ? a.z : a.w;
                        if ((nib >> e) & 1u) {
                            int g = g0 + e;
                            int gi = g / NXY; int rr = g - gi * NXY;
                            int gj = rr / NXQ; int gk = rr - gj * NXQ;
                            if (!SUPPRESSED(gi, gj, gk, p - 1) && f2ord(v) >= bv)
                                cand = g;
                        }
                    }
                }
            } else {
                int lo = (bc == 0) ? 0 : base;
                int hi = base + 128; if (hi > GQ) hi = GQ;
                for (int g = hi - 1 - lane; g >= lo; g -= 32) {
                    if ((s_mw[g >> 5] >> (g & 31)) & 1u) {
                        float v = __ldg(d + g);
                        int gi = g / NXY; int rr = g - gi * NXY;
                        int gj = rr / NXQ; int gk = rr - gj * NXQ;
                        if (!SUPPRESSED(gi, gj, gk, p - 1) && f2ord(v) >= bv)
                            cand = g;
                    }
                }
            }
            unsigned mg = __reduce_min_sync(0xffffffffu, (unsigned)cand);
            if (lane == 0) {
                int pidx = (mg == 0x7FFFFFFFu) ? 0 : (int)mg;
                int pi = pidx / NXY; int rr = pidx - pi * NXY;
                int pj = rr / NXQ;   int pk = rr - pj * NXQ;
                s_pi[p] = pi; s_pj[p] = pj; s_pk[p] = pk;
                s_ps[p] = ord2f(bv);
                s_pv[p] = (bv > ORD_VTH) ? 1 : 0;
            }
        }
        __syncthreads();

        // ---- NMS: flag + recompute affected chunks (value-only, suppressed) ----
        if (s_pv[p] && p < KPICK - 1) {
            const int pi = s_pi[p], pj = s_pj[p], pk = s_pk[p];
            if (tid < 49) {
                int di = tid / 7 - 3, dj = tid % 7 - 3;
                int i = pi + di, j = pj + dj;
                if (i >= 0 && i < NXQ && j >= 0 && j < NXQ) {
                    int kmin = pk - 3 < 0 ? 0 : pk - 3;
                    int kmax = pk + 3 > NXQ - 1 ? NXQ - 1 : pk + 3;
                    int ls = i * NXY + j * NXQ + kmin;
                    int le = ls + (kmax - kmin);
                    s_flag[CHUNK_OF(ls)] = 1;
                    s_flag[CHUNK_OF(le)] = 1;
                }
            }
            __syncthreads();
            int ilo = pi - 3 < 0 ? 0 : pi - 3, ihi = pi + 3 > NXQ - 1 ? NXQ - 1 : pi + 3;
            int jlo = pj - 3 < 0 ? 0 : pj - 3, jhi = pj + 3 > NXQ - 1 ? NXQ - 1 : pj + 3;
            int klo = pk - 3 < 0 ? 0 : pk - 3, khi = pk + 3 > NXQ - 1 ? NXQ - 1 : pk + 3;
            int cmin = CHUNK_OF(ilo * NXY + jlo * NXQ + klo);
            int cmax = CHUNK_OF(ihi * NXY + jhi * NXQ + khi);
            for (int c = cmin + warp; c <= cmax; c += NWARP) {
                if (!s_flag[c]) continue;                 // warp-uniform
                int base = s + (c << 7);
                float bv2 = NEGV;
                bool edge = (c == 0 && s != 0) || (base + 128 > GQ);
                if (!edge) {
                    int g0 = base + (lane << 2);
                    int w = g0 >> 5;
                    unsigned nib = __funnelshift_r(s_mw[w], s_mw[w + 1], g0) & 0xFu;
                    if (nib) {
                        float4 a = __ldg(reinterpret_cast<const float4*>(d + g0));
#pragma unroll
                        for (int e = 0; e < 4; e++) {
                            float v = (e == 0) ? a.x : (e == 1) ? a.y : (e == 2) ? a.z : a.w;
                            if ((nib >> e) & 1u) {
                                int g = g0 + e;
                                int gi = g / NXY; int rr = g - gi * NXY;
                                int gj = rr / NXQ; int gk = rr - gj * NXQ;
                                if (!SUPPRESSED(gi, gj, gk, p)) bv2 = fmaxf(bv2, v);
                            }
                        }
                    }
                } else {
                    int lo = (c == 0) ? 0 : base;
                    int hi = base + 128; if (hi > GQ) hi = GQ;
                    for (int g = lo + lane; g < hi; g += 32) {
                        if ((s_mw[g >> 5] >> (g & 31)) & 1u) {
                            float v = __ldg(d + g);
                            int gi = g / NXY; int rr = g - gi * NXY;
                            int gj = rr / NXQ; int gk = rr - gj * NXQ;
                            if (!SUPPRESSED(gi, gj, gk, p)) bv2 = fmaxf(bv2, v);
                        }
                    }
                }
                unsigned r = __reduce_max_sync(0xffffffffu, f2ord(bv2));
                if (lane == 0) { s_cord[c] = r; s_flag[c] = 0; }
            }
        }
        __syncthreads();
    }

    // ---- epilogue ----
    if (tid < KPICK) {
        int k = tid;
        int n = row / C;
        float m = node_mask[n];
        int v = s_pv[k];
        float x = 0.f, y = 0.f, z = 0.f;
        if (v) { x = s_ax[s_pi[k]]; y = s_ax[s_pj[k]]; z = s_ax[s_pk[k]]; }
        float score = v ? s_ps[k] : NEGV;
        const float* R = Rmats + (long long)n * 9;
        const float* t = tpos + (long long)n * 3;
        float gx = R[0] * x + R[1] * y + R[2] * z + t[0];
        float gy = R[3] * x + R[4] * y + R[5] * z + t[1];
        float gz = R[6] * x + R[7] * y + R[8] * z + t[2];
        long long P  = (long long)rows * KPICK;
        long long rk = (long long)row * KPICK + k;
        out[rk * 3 + 0] = x * m;
        out[rk * 3 + 1] = y * m;
        out[rk * 3 + 2] = z * m;
        out[3 * P + rk * 3 + 0] = gx * m;
        out[3 * P + rk * 3 + 1] = gy * m;
        out[3 * P + rk * 3 + 2] = gz * m;
        out[6 * P + rk] = score * m;
        out[7 * P + rk] = (v && m != 0.0f) ? 1.0f : 0.0f;
    }
}

extern "C" void kernel_launch(void* const* d_in, const int* in_sizes, int n_in,
                              void* d_out, int out_size) {
    // metadata order: density, grid_xyz, sphere_mask, coords_int, Rmats, tpos, node_mask
    const float* density   = (const float*)d_in[0];
    const float* grid_xyz  = (const float*)d_in[1];
    const float* Rmats     = (const float*)d_in[4];
    const float* tpos      = (const float*)d_in[5];
    const float* node_mask = (const float*)d_in[6];
    int rows = in_sizes[0] / GQ;   // B*N*C
    int BN   = in_sizes[6];        // B*N
    int C    = rows / BN;

    build_mask_kernel<<<(MW * 32 + 255) / 256, 256>>>(grid_xyz);
    peaks_kernel<<<rows, NT>>>(density, grid_xyz, Rmats, tpos, node_mask,
                               (float*)d_out, rows, C);
}